// round 2
// baseline (speedup 1.0000x reference)
#include <cuda_runtime.h>
#include <cstdint>

#define BB 128
#define TT 64
#define WW 200
#define EE 128
#define NN 128
#define PADROW 132   // row stride in floats (bank-conflict-free, 16B aligned)

// ---- device scratch (allocation-free) ----
__device__ float g_hpS[BB * TT * EE];   // hp[b,t,n] * |hw[n]|
__device__ float g_u[NN];               // u[e] = sum_n hw[n] * Wq[n,e]

// =====================================================================
// Kernel A: hpS precompute (+ u vector from block 0)
// smem: sWp[128][132] (scaled by |hw|) + sq[64][128]
// =====================================================================
#define SMEM_A_BYTES ((128 * PADROW + 64 * 128) * 4)

__global__ __launch_bounds__(256) void prep_kernel(
    const float* __restrict__ tvecs, const float* __restrict__ W_w,
    const float* __restrict__ h_w, const int* __restrict__ titems)
{
    extern __shared__ float sm[];
    float* sWp = sm;                 // [128][PADROW]
    float* sq  = sm + 128 * PADROW;  // [64][128]
    const int b = blockIdx.x, tid = threadIdx.x;

    // load Wp (first 128 cols of W_w rows), scaled by |hw[row]|
    for (int idx = tid; idx < 128 * 32; idx += 256) {
        int row = idx >> 5, c = idx & 31;
        float4 v = *reinterpret_cast<const float4*>(W_w + row * 256 + c * 4);
        float a = fabsf(h_w[row]);
        v.x *= a; v.y *= a; v.z *= a; v.w *= a;
        *reinterpret_cast<float4*>(sWp + row * PADROW + c * 4) = v;
    }
    // gather q rows
    for (int idx = tid; idx < 64 * 32; idx += 256) {
        int t = idx >> 5, c = idx & 31;
        int it = titems[b * TT + t];
        float4 v = *reinterpret_cast<const float4*>(tvecs + (size_t)it * EE + c * 4);
        *reinterpret_cast<float4*>(sq + t * 128 + c * 4) = v;
    }
    __syncthreads();

    // hpS[t,n] = dot(q[t], WpScaled[n])
    for (int idx = tid; idx < TT * NN; idx += 256) {
        int n = idx & 127, t = idx >> 7;
        const float4* qr = reinterpret_cast<const float4*>(sq + t * 128);
        const float4* wr = reinterpret_cast<const float4*>(sWp + n * PADROW);
        float acc = 0.f;
        #pragma unroll
        for (int c = 0; c < 32; c++) {
            float4 q = qr[c], w = wr[c];
            acc = fmaf(q.x, w.x, acc); acc = fmaf(q.y, w.y, acc);
            acc = fmaf(q.z, w.z, acc); acc = fmaf(q.w, w.w, acc);
        }
        g_hpS[(b * TT + t) * NN + n] = acc;
    }

    // u[e] = sum_n hw[n] * Wq[n,e]  (block 0 only)
    if (b == 0) {
        for (int e = tid; e < EE; e += 256) {
            float acc = 0.f;
            #pragma unroll 8
            for (int n = 0; n < NN; n++)
                acc = fmaf(h_w[n], W_w[n * 256 + 128 + e], acc);
            g_u[e] = acc;
        }
    }
}

// =====================================================================
// Kernel B: per-batch attention. One CTA per b, 512 threads.
// =====================================================================
// smem float offsets
#define OFF_SK 0                       // k       [200][132]
#define OFF_HQ (WW * PADROW)           // hqS     [200][132]  = 26400
#define OFF_UN (2 * WW * PADROW)       // union: Wq tile [16][132] (2112) / satt [16][204] (3264)
#define OFF_SU (OFF_UN + 3264)         // u       [128]
#define OFF_BQ (OFF_SU + 128)          // Bq      [200] (+8 pad)
#define OFF_WB (OFF_BQ + 208)          // Wb*|hw| [128]
#define OFF_MK (OFF_WB + 128)          // mask flags, one byte per w (224B = 56 floats)
#define OFF_MS (OFF_MK + 56)           // misc [8]: [0]=norm
#define SMEM_B_FLOATS (OFF_MS + 8)
#define SMEM_B_BYTES (SMEM_B_FLOATS * 4)

__global__ __launch_bounds__(512) void main_kernel(
    const float* __restrict__ cvecs, const float* __restrict__ W_w,
    const float* __restrict__ W_b,   const float* __restrict__ h_w,
    const int* __restrict__ citems,  const uint32_t* __restrict__ mask,
    float* __restrict__ out)
{
    extern __shared__ float sm[];
    float* sk   = sm + OFF_SK;
    float* shq  = sm + OFF_HQ;
    float* sun  = sm + OFF_UN;
    float* su   = sm + OFF_SU;
    float* sBq  = sm + OFF_BQ;
    float* swb  = sm + OFF_WB;
    unsigned char* smask = reinterpret_cast<unsigned char*>(sm + OFF_MK);
    float* smisc = sm + OFF_MS;

    const int b = blockIdx.x, tid = threadIdx.x;
    const int warp = tid >> 5, lane = tid & 31;

    // ---- phase 1: loads ----
    // mask arrives as a 4-byte-per-element array (int32 or float32 bool);
    // nonzero word == masked. Store 1-byte flags in smem.
    if (tid < WW) smask[tid] = (mask[b * WW + tid] != 0u) ? 1 : 0;
    if (tid >= 256 && tid < 256 + 128) {
        int n = tid - 256;
        swb[n] = W_b[n] * fabsf(h_w[n]);
    }
    if (tid >= 384 && tid < 384 + 32) {
        int c = tid - 384;
        reinterpret_cast<float4*>(su)[c] = reinterpret_cast<const float4*>(g_u)[c];
    }
    for (int r = warp; r < WW; r += 16) {
        int idx = citems[b * WW + r];
        float4 v = reinterpret_cast<const float4*>(cvecs + (size_t)idx * EE)[lane];
        reinterpret_cast<float4*>(sk + r * PADROW)[lane] = v;
    }
    __syncthreads();

    // ---- phase 2: Bq[w] = k[w]·u ; mask count -> norm ----
    if (tid < WW) {
        const float4* kr = reinterpret_cast<const float4*>(sk + tid * PADROW);
        const float4* ur = reinterpret_cast<const float4*>(su);
        float acc = 0.f;
        #pragma unroll
        for (int c = 0; c < 32; c++) {
            float4 k = kr[c], u = ur[c];
            acc = fmaf(k.x, u.x, acc); acc = fmaf(k.y, u.y, acc);
            acc = fmaf(k.z, u.z, acc); acc = fmaf(k.w, u.w, acc);
        }
        sBq[tid] = acc;
    }
    if (warp == 8) {
        int s = 0;
        #pragma unroll
        for (int c = 0; c < 7; c++) {
            int w = lane + 32 * c;
            if (w < WW) s += (int)smask[w];
        }
        #pragma unroll
        for (int o = 16; o; o >>= 1) s += __shfl_xor_sync(0xffffffffu, s, o);
        if (lane == 0) smisc[0] = sqrtf(1000.0f - (float)s);
    }

    // ---- phase 3: hqS = (k·Wq + Wb)*|hw| in 8 n-tiles of 16 ----
    for (int tile = 0; tile < 8; tile++) {
        __syncthreads();   // previous tile's compute done reading sun
        {
            int row = tid >> 5, c = tid & 31;   // 512 threads = 16 rows * 32 chunks
            int n = tile * 16 + row;
            float4 v = *reinterpret_cast<const float4*>(W_w + n * 256 + 128 + c * 4);
            float a = fabsf(h_w[n]);
            v.x *= a; v.y *= a; v.z *= a; v.w *= a;
            reinterpret_cast<float4*>(sun + row * PADROW)[c] = v;
        }
        __syncthreads();
        for (int idx = tid; idx < WW * 4; idx += 512) {
            int w = idx >> 2, nq = idx & 3;          // nq: which float4 of the 16-n tile
            const float4* kr = reinterpret_cast<const float4*>(sk + w * PADROW);
            const float4* w0 = reinterpret_cast<const float4*>(sun + (nq * 4 + 0) * PADROW);
            const float4* w1 = reinterpret_cast<const float4*>(sun + (nq * 4 + 1) * PADROW);
            const float4* w2 = reinterpret_cast<const float4*>(sun + (nq * 4 + 2) * PADROW);
            const float4* w3 = reinterpret_cast<const float4*>(sun + (nq * 4 + 3) * PADROW);
            float4 acc = *reinterpret_cast<const float4*>(swb + tile * 16 + nq * 4);
            #pragma unroll
            for (int c = 0; c < 32; c++) {
                float4 k = kr[c];
                float4 a0 = w0[c], a1 = w1[c], a2 = w2[c], a3 = w3[c];
                acc.x = fmaf(k.x, a0.x, acc.x); acc.x = fmaf(k.y, a0.y, acc.x);
                acc.x = fmaf(k.z, a0.z, acc.x); acc.x = fmaf(k.w, a0.w, acc.x);
                acc.y = fmaf(k.x, a1.x, acc.y); acc.y = fmaf(k.y, a1.y, acc.y);
                acc.y = fmaf(k.z, a1.z, acc.y); acc.y = fmaf(k.w, a1.w, acc.y);
                acc.z = fmaf(k.x, a2.x, acc.z); acc.z = fmaf(k.y, a2.y, acc.z);
                acc.z = fmaf(k.z, a2.z, acc.z); acc.z = fmaf(k.w, a2.w, acc.z);
                acc.w = fmaf(k.x, a3.x, acc.w); acc.w = fmaf(k.y, a3.y, acc.w);
                acc.w = fmaf(k.z, a3.z, acc.w); acc.w = fmaf(k.w, a3.w, acc.w);
            }
            reinterpret_cast<float4*>(shq + w * PADROW)[tile * 4 + nq] = acc;
        }
    }
    __syncthreads();

    // ---- phase 4: per (warp, t): att quad -> softmax -> out ----
    const int j = lane & 7, g = lane >> 3;
    float4 sgn[4];
    #pragma unroll
    for (int c = 0; c < 4; c++) {
        float4 h = reinterpret_cast<const float4*>(h_w)[j + 8 * c];
        sgn[c].x = (h.x >= 0.f) ? 1.f : -1.f;
        sgn[c].y = (h.y >= 0.f) ? 1.f : -1.f;
        sgn[c].z = (h.z >= 0.f) ? 1.f : -1.f;
        sgn[c].w = (h.w >= 0.f) ? 1.f : -1.f;
    }
    const float norm = smisc[0];
    float* satt = sun + warp * 204;

    for (int t = warp; t < TT; t += 16) {
        float4 hp[4];
        const float4* hpr = reinterpret_cast<const float4*>(g_hpS + (b * TT + t) * NN);
        #pragma unroll
        for (int c = 0; c < 4; c++) hp[c] = hpr[j + 8 * c];

        // attention logit partial: S = sum_n sgn * |hpS + hqS|, 4 w's per warp pass
        #pragma unroll 2
        for (int q4 = 0; q4 < 50; q4++) {
            int w = q4 * 4 + g;
            const float4* hr = reinterpret_cast<const float4*>(shq + w * PADROW);
            float acc = 0.f;
            #pragma unroll
            for (int c = 0; c < 4; c++) {
                float4 hq = hr[j + 8 * c];
                float vx = hp[c].x + hq.x;
                float vy = hp[c].y + hq.y;
                float vz = hp[c].z + hq.z;
                float vw = hp[c].w + hq.w;
                acc = fmaf(fabsf(vx), sgn[c].x, acc);
                acc = fmaf(fabsf(vy), sgn[c].y, acc);
                acc = fmaf(fabsf(vz), sgn[c].z, acc);
                acc = fmaf(fabsf(vw), sgn[c].w, acc);
            }
            acc += __shfl_down_sync(0xffffffffu, acc, 4, 8);
            acc += __shfl_down_sync(0xffffffffu, acc, 2, 8);
            acc += __shfl_down_sync(0xffffffffu, acc, 1, 8);
            if (j == 0) satt[w] = acc;
        }
        __syncwarp();

        // softmax (no max-sub: logits are tiny), masked -> 0
        float s = 0.f;
        #pragma unroll
        for (int c = 0; c < 7; c++) {
            int w = lane + 32 * c;
            if (w < WW) {
                float l = 0.5f * (sBq[w] + satt[w]);
                float ev = smask[w] ? 0.f : __expf(l);
                satt[w] = ev;
                s += ev;
            }
        }
        #pragma unroll
        for (int o = 16; o; o >>= 1) s += __shfl_xor_sync(0xffffffffu, s, o);
        __syncwarp();

        // out[e] = (1/(s*norm)) * sum_w exp[w] * k[w][e]; lane owns e = 4*lane..
        float4 o4 = make_float4(0.f, 0.f, 0.f, 0.f);
        #pragma unroll 4
        for (int w = 0; w < WW; w++) {
            float a = satt[w];
            float4 kv = reinterpret_cast<const float4*>(sk + w * PADROW)[lane];
            o4.x = fmaf(a, kv.x, o4.x);
            o4.y = fmaf(a, kv.y, o4.y);
            o4.z = fmaf(a, kv.z, o4.z);
            o4.w = fmaf(a, kv.w, o4.w);
        }
        float scale = 1.0f / (s * norm);
        o4.x *= scale; o4.y *= scale; o4.z *= scale; o4.w *= scale;
        reinterpret_cast<float4*>(out + (b * TT + t) * EE)[lane] = o4;
    }
}

// =====================================================================
extern "C" void kernel_launch(void* const* d_in, const int* in_sizes, int n_in,
                              void* d_out, int out_size)
{
    const float* tvecs = (const float*)d_in[0];
    const float* cvecs = (const float*)d_in[1];
    const float* W_w   = (const float*)d_in[2];
    const float* W_b   = (const float*)d_in[3];
    const float* h_w   = (const float*)d_in[4];
    // d_in[5] = h_b: softmax-invariant, unused
    const int* titems  = (const int*)d_in[6];
    const int* citems  = (const int*)d_in[7];
    const uint32_t* mask = (const uint32_t*)d_in[8];
    float* out = (float*)d_out;

    cudaFuncSetAttribute(prep_kernel, cudaFuncAttributeMaxDynamicSharedMemorySize, SMEM_A_BYTES);
    cudaFuncSetAttribute(main_kernel, cudaFuncAttributeMaxDynamicSharedMemorySize, SMEM_B_BYTES);

    prep_kernel<<<BB, 256, SMEM_A_BYTES>>>(tvecs, W_w, h_w, titems);
    main_kernel<<<BB, 512, SMEM_B_BYTES>>>(cvecs, W_w, W_b, h_w, citems, mask, out);
}

// round 4
// speedup vs baseline: 1.4288x; 1.4288x over previous
#include <cuda_runtime.h>
#include <cstdint>

#define BB 128
#define TT 64
#define WW 200
#define EE 128
#define NN 128
#define PADROW 132   // row stride in floats

typedef unsigned long long u64;

// ---- f32x2 packed helpers ----
__device__ __forceinline__ u64 pk2(float lo, float hi) {
    u64 r; asm("mov.b64 %0,{%1,%2};" : "=l"(r) : "f"(lo), "f"(hi)); return r;
}
__device__ __forceinline__ u64 add2(u64 a, u64 b) {
    u64 r; asm("add.rn.f32x2 %0,%1,%2;" : "=l"(r) : "l"(a), "l"(b)); return r;
}
__device__ __forceinline__ u64 fma2(u64 a, u64 b, u64 c) {
    u64 r; asm("fma.rn.f32x2 %0,%1,%2,%3;" : "=l"(r) : "l"(a), "l"(b), "l"(c)); return r;
}
__device__ __forceinline__ void unpk2(u64 p, float& lo, float& hi) {
    asm("mov.b64 {%0,%1},%2;" : "=f"(lo), "=f"(hi) : "l"(p));
}
union F4U { float4 v; u64 p[2]; float f[4]; };

#define ABS2 0x7FFFFFFF7FFFFFFFULL

// ---- device scratch ----
__device__ float g_hpS[BB * TT * NN];   // hp[b,t,n] * |hw[n]|
__device__ float g_u[NN];               // u[e] = sum_n hw[n] * Wq[n,e]

// =====================================================================
// Kernel A: hpS precompute (+ u vector from block 0)
// =====================================================================
#define SMEM_A_BYTES ((128 * PADROW + 64 * 128) * 4)

__global__ __launch_bounds__(256) void prep_kernel(
    const float* __restrict__ tvecs, const float* __restrict__ W_w,
    const float* __restrict__ h_w, const int* __restrict__ titems)
{
    extern __shared__ float sm[];
    float* sWp = sm;                 // [128][PADROW]
    float* sq  = sm + 128 * PADROW;  // [64][128]
    const int b = blockIdx.x, tid = threadIdx.x;

    for (int idx = tid; idx < 128 * 32; idx += 256) {
        int row = idx >> 5, c = idx & 31;
        float4 v = *reinterpret_cast<const float4*>(W_w + row * 256 + c * 4);
        float a = fabsf(h_w[row]);
        v.x *= a; v.y *= a; v.z *= a; v.w *= a;
        *reinterpret_cast<float4*>(sWp + row * PADROW + c * 4) = v;
    }
    for (int idx = tid; idx < 64 * 32; idx += 256) {
        int t = idx >> 5, c = idx & 31;
        int it = titems[b * TT + t];
        float4 v = *reinterpret_cast<const float4*>(tvecs + (size_t)it * EE + c * 4);
        *reinterpret_cast<float4*>(sq + t * 128 + c * 4) = v;
    }
    __syncthreads();

    for (int idx = tid; idx < TT * NN; idx += 256) {
        int n = idx & 127, t = idx >> 7;
        const F4U* qr = reinterpret_cast<const F4U*>(sq + t * 128);
        const F4U* wr = reinterpret_cast<const F4U*>(sWp + n * PADROW);
        u64 acc = 0;
        #pragma unroll
        for (int c = 0; c < 32; c++) {
            F4U q = qr[c], w = wr[c];
            acc = fma2(q.p[0], w.p[0], acc);
            acc = fma2(q.p[1], w.p[1], acc);
        }
        float lo, hi; unpk2(acc, lo, hi);
        g_hpS[(b * TT + t) * NN + n] = lo + hi;
    }

    if (b == 0) {
        for (int e = tid; e < EE; e += 256) {
            float acc = 0.f;
            #pragma unroll 8
            for (int n = 0; n < NN; n++)
                acc = fmaf(h_w[n], W_w[n * 256 + 128 + e], acc);
            g_u[e] = acc;
        }
    }
}

// =====================================================================
// Kernel B: per-batch attention. One CTA per b, 512 threads.
// =====================================================================
#define OFF_SK 0                       // k       [200][132]
#define OFF_HQ (WW * PADROW)           // hqS     [200][132]; later logits/att at [w*132 + t]
#define OFF_UN (2 * WW * PADROW)       // scratch: Wq pair tile [8][260] = 2080 floats
#define OFF_SU (OFF_UN + 3264)         // u       [128]
#define OFF_BQ (OFF_SU + 128)          // 0.5*Bq  [200] (+8 pad)
#define OFF_WB (OFF_BQ + 208)          // Wb*|hw| [128]
#define OFF_MK (OFF_WB + 128)          // mask flags (1B per w; 56 floats)
#define OFF_MS (OFF_MK + 56)           // misc [8]: [0]=norm
#define SMEM_B_FLOATS (OFF_MS + 8)
#define SMEM_B_BYTES (SMEM_B_FLOATS * 4)
#define PSTRIDE 260                    // pair-row stride (floats)

__global__ __launch_bounds__(512) void main_kernel(
    const float* __restrict__ cvecs, const float* __restrict__ W_w,
    const float* __restrict__ W_b,   const float* __restrict__ h_w,
    const int* __restrict__ citems,  const uint32_t* __restrict__ mask,
    float* __restrict__ out)
{
    extern __shared__ float sm[];
    float* sk    = sm + OFF_SK;
    float* shq   = sm + OFF_HQ;
    float* spair = sm + OFF_UN;
    float* su    = sm + OFF_SU;
    float* sBq   = sm + OFF_BQ;
    float* swb   = sm + OFF_WB;
    unsigned char* smask = reinterpret_cast<unsigned char*>(sm + OFF_MK);
    float* smisc = sm + OFF_MS;

    const int b = blockIdx.x, tid = threadIdx.x;
    const int warp = tid >> 5, lane = tid & 31;

    // ---- phase 1: loads ----
    if (tid < WW) smask[tid] = (mask[b * WW + tid] != 0u) ? 1 : 0;
    if (tid >= 256 && tid < 256 + 128) {
        int n = tid - 256;
        swb[n] = W_b[n] * fabsf(h_w[n]);
    }
    if (tid >= 384 && tid < 384 + 32) {
        int c = tid - 384;
        reinterpret_cast<float4*>(su)[c] = reinterpret_cast<const float4*>(g_u)[c];
    }
    for (int r = warp; r < WW; r += 16) {
        int idx = citems[b * WW + r];
        float4 v = reinterpret_cast<const float4*>(cvecs + (size_t)idx * EE)[lane];
        reinterpret_cast<float4*>(sk + r * PADROW)[lane] = v;
    }
    __syncthreads();

    // ---- phase 2: 0.5*Bq[w] = 0.5*k[w]·u ; mask count -> norm ----
    if (tid < WW) {
        const F4U* kr = reinterpret_cast<const F4U*>(sk + tid * PADROW);
        const F4U* ur = reinterpret_cast<const F4U*>(su);
        u64 acc = 0;
        #pragma unroll
        for (int c = 0; c < 32; c++) {
            F4U k = kr[c], u = ur[c];
            acc = fma2(k.p[0], u.p[0], acc);
            acc = fma2(k.p[1], u.p[1], acc);
        }
        float lo, hi; unpk2(acc, lo, hi);
        sBq[tid] = 0.5f * (lo + hi);
    }
    if (warp == 8) {
        int s = 0;
        #pragma unroll
        for (int c = 0; c < 7; c++) {
            int w = lane + 32 * c;
            if (w < WW) s += (int)smask[w];
        }
        #pragma unroll
        for (int o = 16; o; o >>= 1) s += __shfl_xor_sync(0xffffffffu, s, o);
        if (lane == 0) smisc[0] = sqrtf(1000.0f - (float)s);
    }

    // ---- phase 3: hqS = (k·Wq + Wb)*|hw|, 8 n-tiles of 16, pair-interleaved tile ----
    for (int tile = 0; tile < 8; tile++) {
        __syncthreads();
        {
            int row = tid >> 5, c = tid & 31;  // 16 rows x 32 float4-chunks
            int n = tile * 16 + row;
            F4U v; v.v = *reinterpret_cast<const float4*>(W_w + n * 256 + 128 + c * 4);
            float a = fabsf(h_w[n]);
            int pair = row >> 1, half = row & 1;
            float* pb = spair + pair * PSTRIDE;
            #pragma unroll
            for (int e = 0; e < 4; e++)
                pb[(4 * c + e) * 2 + half] = v.f[e] * a;
        }
        __syncthreads();
        for (int idx = tid; idx < WW * 4; idx += 512) {
            int w = idx >> 2, nq = idx & 3;
            const float4* kr = reinterpret_cast<const float4*>(sk + w * PADROW);
            const F4U* pA = reinterpret_cast<const F4U*>(spair + (2 * nq) * PSTRIDE);
            const F4U* pB = reinterpret_cast<const F4U*>(spair + (2 * nq + 1) * PSTRIDE);
            u64 acc01 = *reinterpret_cast<const u64*>(swb + tile * 16 + nq * 4);
            u64 acc23 = *reinterpret_cast<const u64*>(swb + tile * 16 + nq * 4 + 2);
            #pragma unroll
            for (int c = 0; c < 32; c++) {
                float4 k = kr[c];
                F4U a0 = pA[2 * c], a1 = pA[2 * c + 1];  // pairs (n0,n1) for e=4c..4c+3
                F4U b0 = pB[2 * c], b1 = pB[2 * c + 1];  // pairs (n2,n3)
                u64 kx = pk2(k.x, k.x), ky = pk2(k.y, k.y);
                u64 kz = pk2(k.z, k.z), kw = pk2(k.w, k.w);
                acc01 = fma2(kx, a0.p[0], acc01);
                acc01 = fma2(ky, a0.p[1], acc01);
                acc01 = fma2(kz, a1.p[0], acc01);
                acc01 = fma2(kw, a1.p[1], acc01);
                acc23 = fma2(kx, b0.p[0], acc23);
                acc23 = fma2(ky, b0.p[1], acc23);
                acc23 = fma2(kz, b1.p[0], acc23);
                acc23 = fma2(kw, b1.p[1], acc23);
            }
            F4U r; r.p[0] = acc01; r.p[1] = acc23;
            reinterpret_cast<float4*>(shq + w * PADROW)[tile * 4 + nq] = r.v;
        }
    }
    __syncthreads();

    // ---- phase 4a: logits, w-sliced per warp, hq in registers across all t ----
    // warp v owns quads [qs, qe): 50 quads over 16 warps (warps 0,1 get 4; rest 3).
    const int j = lane & 7, g = lane >> 3;
    u64 sgn2[8];
    #pragma unroll
    for (int c = 0; c < 4; c++) {
        F4U h; h.v = reinterpret_cast<const float4*>(h_w)[j + 8 * c];
        sgn2[2 * c]     = pk2(h.f[0] >= 0.f ? 0.5f : -0.5f, h.f[1] >= 0.f ? 0.5f : -0.5f);
        sgn2[2 * c + 1] = pk2(h.f[2] >= 0.f ? 0.5f : -0.5f, h.f[3] >= 0.f ? 0.5f : -0.5f);
    }
    {
        const int qs = (warp < 2) ? warp * 4 : 8 + 3 * (warp - 2);
        const int qe = qs + ((warp < 2) ? 4 : 3);
        const float* hpbase = g_hpS + (size_t)b * TT * NN;

        for (int q = qs; q < qe; q++) {
            const int w = 4 * q + g;
            // hq row w -> registers (8 u64)
            u64 hq2[8];
            {
                const float4* hr = reinterpret_cast<const float4*>(shq + w * PADROW);
                #pragma unroll
                for (int c = 0; c < 4; c++) {
                    F4U x; x.v = hr[j + 8 * c];
                    hq2[2 * c] = x.p[0]; hq2[2 * c + 1] = x.p[1];
                }
            }
            #pragma unroll 2
            for (int tg = 0; tg < 16; tg++) {
                // load hp for 4 t's
                u64 hp2[4][8];
                #pragma unroll
                for (int tt = 0; tt < 4; tt++) {
                    const float4* hpr = reinterpret_cast<const float4*>(hpbase + (tg * 4 + tt) * NN);
                    #pragma unroll
                    for (int c = 0; c < 4; c++) {
                        F4U x; x.v = hpr[j + 8 * c];
                        hp2[tt][2 * c] = x.p[0]; hp2[tt][2 * c + 1] = x.p[1];
                    }
                }
                #pragma unroll
                for (int tt = 0; tt < 4; tt++) {
                    u64 acc = 0;
                    #pragma unroll
                    for (int c2 = 0; c2 < 8; c2++) {
                        u64 v = add2(hp2[tt][c2], hq2[c2]);
                        v &= ABS2;
                        acc = fma2(v, sgn2[c2], acc);
                    }
                    float lo, hi; unpk2(acc, lo, hi);
                    float s = lo + hi;
                    s += __shfl_down_sync(0xffffffffu, s, 4, 8);
                    s += __shfl_down_sync(0xffffffffu, s, 2, 8);
                    s += __shfl_down_sync(0xffffffffu, s, 1, 8);
                    if (j == 0) shq[w * PADROW + tg * 4 + tt] = s;  // overwrite dead hq row
                }
            }
        }
    }
    __syncthreads();

    // ---- phase 4b: softmax + out; warp v owns t = 4v..4v+3 ----
    const float norm = smisc[0];
    float sum[4];
    #pragma unroll
    for (int tt = 0; tt < 4; tt++) {
        const int t = warp * 4 + tt;
        float s = 0.f;
        #pragma unroll
        for (int c = 0; c < 7; c++) {
            int w = lane + 32 * c;
            if (w < WW) {
                float l = sBq[w] + shq[w * PADROW + t];
                float ev = smask[w] ? 0.f : __expf(l);
                shq[w * PADROW + t] = ev;
                s += ev;
            }
        }
        #pragma unroll
        for (int o = 16; o; o >>= 1) s += __shfl_xor_sync(0xffffffffu, s, o);
        sum[tt] = s;
    }
    __syncwarp();

    u64 o2[4][2] = {};
    #pragma unroll 4
    for (int w = 0; w < WW; w++) {
        F4U a4; a4.v = *reinterpret_cast<const float4*>(shq + w * PADROW + warp * 4); // att for 4 t (bcast)
        F4U kv; kv.v = reinterpret_cast<const float4*>(sk + w * PADROW)[lane];
        #pragma unroll
        for (int tt = 0; tt < 4; tt++) {
            u64 av = pk2(a4.f[tt], a4.f[tt]);
            o2[tt][0] = fma2(av, kv.p[0], o2[tt][0]);
            o2[tt][1] = fma2(av, kv.p[1], o2[tt][1]);
        }
    }
    #pragma unroll
    for (int tt = 0; tt < 4; tt++) {
        const int t = warp * 4 + tt;
        float scale = 1.0f / (sum[tt] * norm);
        F4U r;
        unpk2(o2[tt][0], r.f[0], r.f[1]);
        unpk2(o2[tt][1], r.f[2], r.f[3]);
        r.f[0] *= scale; r.f[1] *= scale; r.f[2] *= scale; r.f[3] *= scale;
        reinterpret_cast<float4*>(out + (size_t)(b * TT + t) * EE)[lane] = r.v;
    }
}

// =====================================================================
extern "C" void kernel_launch(void* const* d_in, const int* in_sizes, int n_in,
                              void* d_out, int out_size)
{
    const float* tvecs = (const float*)d_in[0];
    const float* cvecs = (const float*)d_in[1];
    const float* W_w   = (const float*)d_in[2];
    const float* W_b   = (const float*)d_in[3];
    const float* h_w   = (const float*)d_in[4];
    // d_in[5] = h_b: softmax-invariant, unused
    const int* titems  = (const int*)d_in[6];
    const int* citems  = (const int*)d_in[7];
    const uint32_t* mask = (const uint32_t*)d_in[8];
    float* out = (float*)d_out;

    cudaFuncSetAttribute(prep_kernel, cudaFuncAttributeMaxDynamicSharedMemorySize, SMEM_A_BYTES);
    cudaFuncSetAttribute(main_kernel, cudaFuncAttributeMaxDynamicSharedMemorySize, SMEM_B_BYTES);

    prep_kernel<<<BB, 256, SMEM_A_BYTES>>>(tvecs, W_w, h_w, titems);
    main_kernel<<<BB, 512, SMEM_B_BYTES>>>(cvecs, W_w, W_b, h_w, citems, mask, out);
}